// round 5
// baseline (speedup 1.0000x reference)
#include <cuda_runtime.h>

// LSTM (B=4096, T=512, I=5, H=16). Reference output = sigmoid(h_final[-1] @ W_lin.T + b_lin)
// -> depends ONLY on batch element B-1. One sequence, one warp, pure serial latency.
//
// Layout: logical lane u (=l&15) computes ALL four gates (i,f,g,o) of hidden
// unit u — no post-activation cross-lane traffic; the only shuffles are the 16
// h-broadcasts feeding the recurrent matvec. Lanes 16-31 mirror 0-15.
// Gate rows in W (4H=64): i=u, f=u+16, g=u+32, o=u+48.
//
// Sigmoid gates: sigma(x) = 0.5 + 0.5*tanh(x/2), /2 folded into pre-scaled
// weights -> one MUFU.TANH + FMA per gate. MUFU issue order f,i,g,o keeps the
// ig->c->tanh(c)->h tail minimal (MUFU rt_SMSP=8).
//
// Input projection xp(t+1) is software-pipelined one step ahead so its
// LDS(29)+FMA chain never sits at the head of the h-dependent matvec.

#define BB 4096
#define TT 512
#define II 5
#define HH 16

typedef unsigned long long u64;

__device__ __forceinline__ u64 pack2(float a, float b) {
    u64 r; asm("mov.b64 %0, {%1, %2};" : "=l"(r) : "f"(a), "f"(b)); return r;
}
__device__ __forceinline__ void unpack2(float& a, float& b, u64 r) {
    asm("mov.b64 {%0, %1}, %2;" : "=f"(a), "=f"(b) : "l"(r));
}
__device__ __forceinline__ u64 fma2(u64 a, u64 b, u64 c) {
    u64 d; asm("fma.rn.f32x2 %0, %1, %2, %3;" : "=l"(d) : "l"(a), "l"(b), "l"(c)); return d;
}
__device__ __forceinline__ u64 add2(u64 a, u64 b) {
    u64 d; asm("add.rn.f32x2 %0, %1, %2;" : "=l"(d) : "l"(a), "l"(b)); return d;
}
// MUFU.TANH: lat 16, max abs err ~5e-4.
__device__ __forceinline__ float tanh_mufu(float x) {
    float y; asm("tanh.approx.f32 %0, %1;" : "=f"(y) : "f"(x)); return y;
}
// Accurate sigmoid for the single final output.
__device__ __forceinline__ float sigmoid_acc(float x) {
    return __fdividef(1.0f, 1.0f + __expf(-x));
}

__global__ void __launch_bounds__(32, 1)
lstm_last_kernel(const float* __restrict__ x,
                 const float* __restrict__ W_ih,
                 const float* __restrict__ W_hh,
                 const float* __restrict__ b_ih,
                 const float* __restrict__ b_hh,
                 const float* __restrict__ W_lin,
                 const float* __restrict__ b_lin,
                 float* __restrict__ out)
{
    __shared__ float xs[TT * II + 8];   // +8 pad: pipelined t+1 load needs no guard
    __shared__ float hs[HH];

    const int l = threadIdx.x;
    const int u = l & 15;               // hidden unit owned by this lane
    const unsigned FULL = 0xffffffffu;

    // Stage x[B-1,:,:] (2560 floats = 640 float4; base 16B-aligned: 4095*2560*4)
    {
        const float4* xr4 = reinterpret_cast<const float4*>(
            x + (size_t)(BB - 1) * TT * II);
        float4* xs4 = reinterpret_cast<float4*>(xs);
        #pragma unroll
        for (int i = l; i < (TT * II) / 4; i += 32) xs4[i] = xr4[i];
        if (l < 8) xs[TT * II + l] = 0.0f;   // pad
    }

    // Gate rows for unit u
    const int gI = u, gF = u + 16, gG = u + 32, gO = u + 48;

    // Packed recurrent weights; sigmoid rows (i,f,o) pre-scaled by 0.5 so the
    // accumulator directly yields x/2 for sigma(x)=0.5+0.5*tanh(x/2).
    u64 wIF[HH], wGO[HH], uIF[II], uGO[II];
    #pragma unroll
    for (int k = 0; k < HH; k++) {
        wIF[k] = pack2(0.5f * W_hh[gI * HH + k], 0.5f * W_hh[gF * HH + k]);
        wGO[k] = pack2(       W_hh[gG * HH + k], 0.5f * W_hh[gO * HH + k]);
    }
    #pragma unroll
    for (int i = 0; i < II; i++) {
        uIF[i] = pack2(0.5f * W_ih[gI * II + i], 0.5f * W_ih[gF * II + i]);
        uGO[i] = pack2(       W_ih[gG * II + i], 0.5f * W_ih[gO * II + i]);
    }
    const u64 bIF = pack2(0.5f * (b_ih[gI] + b_hh[gI]),
                          0.5f * (b_ih[gF] + b_hh[gF]));
    const u64 bGO = pack2(        b_ih[gG] + b_hh[gG],
                          0.5f * (b_ih[gO] + b_hh[gO]));

    __syncwarp();

    float h = 0.0f, c = 0.0f;

    // Pipelined input projection for t=0
    u64 xpIF = bIF, xpGO = bGO;
    #pragma unroll
    for (int i = 0; i < II; i++) {
        u64 xv2 = pack2(xs[i], xs[i]);
        xpIF = fma2(xv2, uIF[i], xpIF);
        xpGO = fma2(xv2, uGO[i], xpGO);
    }

    #pragma unroll 2
    for (int t = 0; t < TT; t++) {
        // ---- issue next-step x loads immediately (LDS lat 29, fully hidden)
        float xn[II];
        {
            const float* xtn = &xs[(t + 1) * II];
            #pragma unroll
            for (int i = 0; i < II; i++) xn[i] = xtn[i];
        }

        // ---- recurrent matvec: accs seeded with the PRE-COMPUTED xp(t), so
        //      the first h-dependent fma has no input-proj chain ahead of it.
        u64 aIF0 = xpIF, aGO0 = xpGO, aIF1 = 0, aGO1 = 0;
        #pragma unroll
        for (int k = 0; k < HH; k += 2) {
            float h0 = __shfl_sync(FULL, h, k);
            float h1 = __shfl_sync(FULL, h, k + 1);
            u64 h02 = pack2(h0, h0);
            u64 h12 = pack2(h1, h1);
            aIF0 = fma2(h02, wIF[k],     aIF0);
            aIF1 = fma2(h12, wIF[k + 1], aIF1);
            aGO0 = fma2(h02, wGO[k],     aGO0);
            aGO1 = fma2(h12, wGO[k + 1], aGO1);
        }
        float aI2, aF2, aG, aO2;            // aI2/aF2/aO2 hold x/2 (pre-scaled)
        unpack2(aI2, aF2, add2(aIF0, aIF1));
        unpack2(aG,  aO2, add2(aGO0, aGO1));

        // ---- activations; MUFU order f,i,g,o (rt=8 port, f first on chain)
        float tf = tanh_mufu(aF2);
        float ti = tanh_mufu(aI2);
        float tg = tanh_mufu(aG);
        float to = tanh_mufu(aO2);
        float fv = fmaf(0.5f, tf, 0.5f);
        float iv = fmaf(0.5f, ti, 0.5f);
        float ov = fmaf(0.5f, to, 0.5f);

        // ---- next-step input projection (independent; hides under MUFU waits)
        xpIF = bIF; xpGO = bGO;
        #pragma unroll
        for (int i = 0; i < II; i++) {
            u64 xv2 = pack2(xn[i], xn[i]);
            xpIF = fma2(xv2, uIF[i], xpIF);
            xpGO = fma2(xv2, uGO[i], xpGO);
        }

        // ---- state update
        c = fmaf(fv, c, iv * tg);      // c = f*c + i*g
        h = ov * tanh_mufu(c);         // h = o * tanh(c)
    }

    if (l < HH) hs[l] = h;
    __syncwarp();

    if (l < 5) {
        float acc = b_lin[l];
        #pragma unroll
        for (int k = 0; k < HH; k++)
            acc = fmaf(W_lin[l * HH + k], hs[k], acc);
        out[l] = sigmoid_acc(acc);     // accurate path for the single final sigmoid
    }
}

extern "C" void kernel_launch(void* const* d_in, const int* in_sizes, int n_in,
                              void* d_out, int out_size)
{
    const float* x     = (const float*)d_in[0];
    const float* W_ih  = (const float*)d_in[1];
    const float* W_hh  = (const float*)d_in[2];
    const float* b_ih  = (const float*)d_in[3];
    const float* b_hh  = (const float*)d_in[4];
    const float* W_lin = (const float*)d_in[5];
    const float* b_lin = (const float*)d_in[6];

    lstm_last_kernel<<<1, 32>>>(x, W_ih, W_hh, b_ih, b_hh, W_lin, b_lin,
                                (float*)d_out);
}

// round 8
// speedup vs baseline: 1.4480x; 1.4480x over previous
#include <cuda_runtime.h>

// LSTM (B=4096, T=512, I=5, H=16). Reference output = sigmoid(h_final[-1] @ W_lin.T + b_lin)
// -> depends ONLY on batch element B-1. One sequence; recurrence on one warp.
//
// Warp 0 runs the 512-step recurrence. Warps 1-15 precompute ALL input
// projections xp(t) in parallel (h-independent) into a 128 KB dynamic-smem
// table of packed {iF,gO} f32x2 seeds, then exit -- warp 0's per-step
// __syncthreads drops to the nw=1 floor (~3 cyc) and its loop loses the
// 10 fma2 + 5 LDS of in-loop projection (one LDS.128 instead).
//
// h broadcast: double-buffered dup-pair smem (hd[b][k]={h_k,h_k}): STS.64 +
// BAR + 8 LDS.128 per step. No shuffles, no pack MOVs anywhere in the loop.
// Matvec issues all 16 IF fma2 BEFORE the 16 GO fma2 so MUFU f/i overlap the
// GO issue block (MUFU rt=8 serialization starts ~32 cyc earlier).
// Sigmoid gates: sigma(x)=0.5+0.5*tanh(x/2), /2 folded into i/f/o weights.

#define BB 4096
#define TT 512
#define II 5
#define HH 16

typedef unsigned long long u64;

__device__ __forceinline__ u64 pack2(float a, float b) {
    u64 r; asm("mov.b64 %0, {%1, %2};" : "=l"(r) : "f"(a), "f"(b)); return r;
}
__device__ __forceinline__ void unpack2(float& a, float& b, u64 r) {
    asm("mov.b64 {%0, %1}, %2;" : "=f"(a), "=f"(b) : "l"(r));
}
__device__ __forceinline__ u64 fma2(u64 a, u64 b, u64 c) {
    u64 d; asm("fma.rn.f32x2 %0, %1, %2, %3;" : "=l"(d) : "l"(a), "l"(b), "l"(c)); return d;
}
__device__ __forceinline__ u64 add2(u64 a, u64 b) {
    u64 d; asm("add.rn.f32x2 %0, %1, %2;" : "=l"(d) : "l"(a), "l"(b)); return d;
}
__device__ __forceinline__ float tanh_mufu(float x) {       // MUFU.TANH lat 16
    float y; asm("tanh.approx.f32 %0, %1;" : "=f"(y) : "f"(x)); return y;
}
__device__ __forceinline__ float sigmoid_acc(float x) {     // final output only
    return __fdividef(1.0f, 1.0f + __expf(-x));
}

__global__ void __launch_bounds__(512, 1)
lstm_last_kernel(const float* __restrict__ x,
                 const float* __restrict__ W_ih,
                 const float* __restrict__ W_hh,
                 const float* __restrict__ b_ih,
                 const float* __restrict__ b_hh,
                 const float* __restrict__ W_lin,
                 const float* __restrict__ b_lin,
                 float* __restrict__ out)
{
    // xq[t][u] = {xpIF, xpGO} packed seeds, 16 B per (t,u): 512*16*16 = 128 KB
    extern __shared__ __align__(16) u64 xq[];
    __shared__ __align__(16) u64 hd[2][HH];     // dup h pairs, double-buffered

    const int l   = threadIdx.x;
    const int wid = l >> 5;
    const int u   = (l & 31) & 15;              // unit owned by this lane

    // Gate rows for unit u (gate order i,f,g,o in 4H=64)
    const int gI = u, gF = u + 16, gG = u + 32, gO = u + 48;

    if (wid != 0) {
        // ---- producer warps: input projections for t = wid-1, wid-1+15, ...
        u64 uIF[II], uGO[II];
        #pragma unroll
        for (int i = 0; i < II; i++) {
            uIF[i] = pack2(0.5f * W_ih[gI * II + i], 0.5f * W_ih[gF * II + i]);
            uGO[i] = pack2(       W_ih[gG * II + i], 0.5f * W_ih[gO * II + i]);
        }
        const u64 bIF = pack2(0.5f * (b_ih[gI] + b_hh[gI]),
                              0.5f * (b_ih[gF] + b_hh[gF]));
        const u64 bGO = pack2(        b_ih[gG] + b_hh[gG],
                              0.5f * (b_ih[gO] + b_hh[gO]));

        const float* xb = x + (size_t)(BB - 1) * TT * II;
        for (int t = wid - 1; t < TT; t += 15) {
            const float* xt = xb + t * II;
            u64 aIF = bIF, aGO = bGO;
            #pragma unroll
            for (int i = 0; i < II; i++) {
                float xv = __ldg(xt + i);
                u64 xv2 = pack2(xv, xv);
                aIF = fma2(xv2, uIF[i], aIF);
                aGO = fma2(xv2, uGO[i], aGO);
            }
            // mirror lanes write identical bits to the same address: benign
            ulonglong2* dst = reinterpret_cast<ulonglong2*>(&xq[(t * HH + u) * 2]);
            *dst = make_ulonglong2(aIF, aGO);
        }
        __syncthreads();    // publish xq (BAR drains STS), then vanish
        return;             // exited threads are not counted by later bar.sync
    }

    // ---- warp 0: recurrence
    if (l < HH) { hd[0][l] = 0; hd[1][l] = 0; }

    // Recurrent weights; sigmoid rows (i,f,o) pre-scaled by 0.5
    u64 wIF[HH], wGO[HH];
    #pragma unroll
    for (int k = 0; k < HH; k++) {
        wIF[k] = pack2(0.5f * W_hh[gI * HH + k], 0.5f * W_hh[gF * HH + k]);
        wGO[k] = pack2(       W_hh[gG * HH + k], 0.5f * W_hh[gO * HH + k]);
    }

    __syncthreads();        // xq ready; producers exit after this

    float c = 0.0f;

    #pragma unroll 4
    for (int t = 0; t < TT; t++) {
        const int cur = t & 1;
        // nw=1 barrier (floor ~3): orders prev STS of h before LDS below
        __syncthreads();

        // xp seeds: one LDS.128
        ulonglong2 sq = *reinterpret_cast<const ulonglong2*>(&xq[(t * HH + u) * 2]);

        // 16 {h_k,h_k} pairs via 8 LDS.128 (broadcast, conflict-free)
        u64 hp[HH];
        #pragma unroll
        for (int k = 0; k < HH; k += 2) {
            ulonglong2 q = *reinterpret_cast<const ulonglong2*>(&hd[cur][k]);
            hp[k] = q.x; hp[k + 1] = q.y;
        }

        // Matvec: ALL IF fmas first (aI/aF finish ~32 cyc early), then GO.
        u64 aIF0 = sq.x, aIF1 = 0;
        #pragma unroll
        for (int k = 0; k < HH; k += 2) {
            aIF0 = fma2(hp[k],     wIF[k],     aIF0);
            aIF1 = fma2(hp[k + 1], wIF[k + 1], aIF1);
        }
        float aI2, aF2;                 // hold x/2 (weights pre-scaled)
        unpack2(aI2, aF2, add2(aIF0, aIF1));
        float tf = tanh_mufu(aF2);      // issues under the GO block below
        float ti = tanh_mufu(aI2);

        u64 aGO0 = sq.y, aGO1 = 0;
        #pragma unroll
        for (int k = 0; k < HH; k += 2) {
            aGO0 = fma2(hp[k],     wGO[k],     aGO0);
            aGO1 = fma2(hp[k + 1], wGO[k + 1], aGO1);
        }
        float aG, aO2;
        unpack2(aG, aO2, add2(aGO0, aGO1));
        float tg = tanh_mufu(aG);
        float to = tanh_mufu(aO2);

        float fv = fmaf(0.5f, tf, 0.5f);
        float iv = fmaf(0.5f, ti, 0.5f);
        float ov = fmaf(0.5f, to, 0.5f);

        c = fmaf(fv, c, iv * tg);       // c = f*c + i*g
        float h = ov * tanh_mufu(c);    // h = o * tanh(c)
        hd[cur ^ 1][u] = pack2(h, h);   // unconditional: mirrors write same bits
    }

    __syncthreads();
    // Final h pairs live in hd[0] (last store: t=511 -> cur=1 -> nxt=0)
    if (l < 5) {
        float acc = b_lin[l];
        #pragma unroll
        for (int k = 0; k < HH; k++) {
            float hk, dummy;
            unpack2(hk, dummy, hd[0][k]);
            acc = fmaf(W_lin[l * HH + k], hk, acc);
        }
        out[l] = sigmoid_acc(acc);
    }
}

extern "C" void kernel_launch(void* const* d_in, const int* in_sizes, int n_in,
                              void* d_out, int out_size)
{
    const float* x     = (const float*)d_in[0];
    const float* W_ih  = (const float*)d_in[1];
    const float* W_hh  = (const float*)d_in[2];
    const float* b_ih  = (const float*)d_in[3];
    const float* b_hh  = (const float*)d_in[4];
    const float* W_lin = (const float*)d_in[5];
    const float* b_lin = (const float*)d_in[6];

    const int smem_bytes = TT * HH * 2 * (int)sizeof(u64);   // 128 KB
    cudaFuncSetAttribute(lstm_last_kernel,
                         cudaFuncAttributeMaxDynamicSharedMemorySize, smem_bytes);
    lstm_last_kernel<<<1, 512, smem_bytes>>>(x, W_ih, W_hh, b_ih, b_hh,
                                             W_lin, b_lin, (float*)d_out);
}

// round 9
// speedup vs baseline: 1.5339x; 1.0593x over previous
#include <cuda_runtime.h>

// LSTM (B=4096, T=512, I=5, H=16). Output = sigmoid(h_final[-1] @ W_lin.T + b_lin)
// -> depends ONLY on batch element B-1. One sequence; recurrence on warp 0.
//
// R9: gate-pair split across warp halves. Lane l: u=l&15; half0 (l<16)
// accumulates the (i,f) f32x2 pair, half1 the (g,o) pair -> 16 fma2/lane/step
// (was 32; fma-pipe issue at rt=2 was the binding cost at 1 warp/SMSP).
// The two accumulator pairs are swapped with ONE shfl.xor(16) of the packed
// u64 BEFORE activations; own-pair MUFU.TANHs issue under the shuffle flight;
// 4 SELs re-sort (i,f,g,o). Both halves then compute identical c,h.
//
// Warps 1-15 precompute all input projections xp(t) into a 128 KB smem table,
// then exit (later bar.sync counts only live warps). h broadcast stays the
// double-buffered dup-pair smem scheme: STS.64 + BAR + 8 LDS.128.
// Sigmoids: sigma(x)=0.5+0.5*tanh(x/2), /2 folded into i/f/o weight rows.

#define BB 4096
#define TT 512
#define II 5
#define HH 16

typedef unsigned long long u64;

__device__ __forceinline__ u64 pack2(float a, float b) {
    u64 r; asm("mov.b64 %0, {%1, %2};" : "=l"(r) : "f"(a), "f"(b)); return r;
}
__device__ __forceinline__ void unpack2(float& a, float& b, u64 r) {
    asm("mov.b64 {%0, %1}, %2;" : "=f"(a), "=f"(b) : "l"(r));
}
__device__ __forceinline__ u64 fma2(u64 a, u64 b, u64 c) {
    u64 d; asm("fma.rn.f32x2 %0, %1, %2, %3;" : "=l"(d) : "l"(a), "l"(b), "l"(c)); return d;
}
__device__ __forceinline__ u64 add2(u64 a, u64 b) {
    u64 d; asm("add.rn.f32x2 %0, %1, %2;" : "=l"(d) : "l"(a), "l"(b)); return d;
}
__device__ __forceinline__ float tanh_mufu(float x) {       // MUFU.TANH lat 16
    float y; asm("tanh.approx.f32 %0, %1;" : "=f"(y) : "f"(x)); return y;
}
__device__ __forceinline__ float sigmoid_acc(float x) {     // final output only
    return __fdividef(1.0f, 1.0f + __expf(-x));
}

__global__ void __launch_bounds__(512, 1)
lstm_last_kernel(const float* __restrict__ x,
                 const float* __restrict__ W_ih,
                 const float* __restrict__ W_hh,
                 const float* __restrict__ b_ih,
                 const float* __restrict__ b_hh,
                 const float* __restrict__ W_lin,
                 const float* __restrict__ b_lin,
                 float* __restrict__ out)
{
    // xq[(t*16+u)*2 + half] = packed xp pair for (t, unit u, gate-pair half)
    extern __shared__ __align__(16) u64 xq[];
    __shared__ __align__(16) u64 hd[2][HH];     // dup h pairs, double-buffered

    const int l   = threadIdx.x;
    const int wid = l >> 5;
    const int u   = (l & 31) & 15;
    const bool hi = ((l & 31) >> 4) != 0;       // half1 owns (g,o)

    // Gate rows for unit u (gate order i,f,g,o in 4H=64)
    const int gI = u, gF = u + 16, gG = u + 32, gO = u + 48;

    if (wid != 0) {
        // ---- producer warps: xp(t) for t = wid-1, wid-1+15, ...
        u64 uIF[II], uGO[II];
        #pragma unroll
        for (int i = 0; i < II; i++) {
            uIF[i] = pack2(0.5f * W_ih[gI * II + i], 0.5f * W_ih[gF * II + i]);
            uGO[i] = pack2(       W_ih[gG * II + i], 0.5f * W_ih[gO * II + i]);
        }
        const u64 bIF = pack2(0.5f * (b_ih[gI] + b_hh[gI]),
                              0.5f * (b_ih[gF] + b_hh[gF]));
        const u64 bGO = pack2(        b_ih[gG] + b_hh[gG],
                              0.5f * (b_ih[gO] + b_hh[gO]));

        const float* xb = x + (size_t)(BB - 1) * TT * II;
        for (int t = wid - 1; t < TT; t += 15) {
            const float* xt = xb + t * II;
            u64 aIF = bIF, aGO = bGO;
            #pragma unroll
            for (int i = 0; i < II; i++) {
                float xv = __ldg(xt + i);
                u64 xv2 = pack2(xv, xv);
                aIF = fma2(xv2, uIF[i], aIF);
                aGO = fma2(xv2, uGO[i], aGO);
            }
            // mirror lanes write identical bits: benign dup
            *reinterpret_cast<ulonglong2*>(&xq[(t * HH + u) * 2]) =
                make_ulonglong2(aIF, aGO);
        }
        __syncthreads();    // publish xq, then vanish
        return;
    }

    // ---- warp 0: recurrence
    if (l < HH) { hd[0][l] = 0; hd[1][l] = 0; }

    // This lane's recurrent weight pair: half0 -> (0.5*Wi, 0.5*Wf),
    // half1 -> (Wg, 0.5*Wo).
    u64 wP[HH];
    #pragma unroll
    for (int k = 0; k < HH; k++) {
        wP[k] = hi ? pack2(       W_hh[gG * HH + k], 0.5f * W_hh[gO * HH + k])
                   : pack2(0.5f * W_hh[gI * HH + k], 0.5f * W_hh[gF * HH + k]);
    }
    const int seed_off = hi ? 1 : 0;

    __syncthreads();        // xq ready; producers exit

    const unsigned FULL = 0xffffffffu;
    float c = 0.0f;

    #pragma unroll 4
    for (int t = 0; t < TT; t++) {
        const int cur = t & 1;
        // nw=1 barrier: orders prev STS of h before the LDS below
        __syncthreads();

        // Own xp seed pair: one LDS.64
        u64 seed = xq[(t * HH + u) * 2 + seed_off];

        // 16 {h_k,h_k} pairs via 8 LDS.128 (broadcast, conflict-free)
        u64 hp[HH];
        #pragma unroll
        for (int k = 0; k < HH; k += 2) {
            ulonglong2 q = *reinterpret_cast<const ulonglong2*>(&hd[cur][k]);
            hp[k] = q.x; hp[k + 1] = q.y;
        }

        // Matvec: 16 fma2 (2 accumulators, depth 8)
        u64 a0 = seed, a1 = 0;
        #pragma unroll
        for (int k = 0; k < HH; k += 2) {
            a0 = fma2(hp[k],     wP[k],     a0);
            a1 = fma2(hp[k + 1], wP[k + 1], a1);
        }
        u64 accP = add2(a0, a1);

        // Butterfly: swap accumulator pairs between halves (2 SASS SHFLs)
        u64 accX = __shfl_xor_sync(FULL, accP, 16);

        // Own-pair activations issue under the shuffle flight
        float p0, p1, q0, q1;
        unpack2(p0, p1, accP);          // half0: (aI/2, aF/2); half1: (aG, aO/2)
        float tp0 = tanh_mufu(p0);
        float tp1 = tanh_mufu(p1);
        unpack2(q0, q1, accX);          // the other pair
        float tq0 = tanh_mufu(q0);
        float tq1 = tanh_mufu(q1);

        // Re-sort to (i,f,g,o) — 4 SELs on the alu pipe
        float tI = hi ? tq0 : tp0;
        float tF = hi ? tq1 : tp1;
        float tG = hi ? tp0 : tq0;
        float tO = hi ? tp1 : tq1;

        float iv = fmaf(0.5f, tI, 0.5f);
        float fv = fmaf(0.5f, tF, 0.5f);
        float ov = fmaf(0.5f, tO, 0.5f);

        c = fmaf(fv, c, iv * tG);       // c = f*c + i*g
        float h = ov * tanh_mufu(c);    // h = o * tanh(c)
        hd[cur ^ 1][u] = pack2(h, h);   // both halves write identical bits
    }

    __syncthreads();
    // Final h pairs in hd[0] (last store: t=511 -> cur=1 -> nxt=0)
    if (l < 5) {
        float acc = b_lin[l];
        #pragma unroll
        for (int k = 0; k < HH; k++) {
            float hk, dummy;
            unpack2(hk, dummy, hd[0][k]);
            acc = fmaf(W_lin[l * HH + k], hk, acc);
        }
        out[l] = sigmoid_acc(acc);
    }
}

extern "C" void kernel_launch(void* const* d_in, const int* in_sizes, int n_in,
                              void* d_out, int out_size)
{
    const float* x     = (const float*)d_in[0];
    const float* W_ih  = (const float*)d_in[1];
    const float* W_hh  = (const float*)d_in[2];
    const float* b_ih  = (const float*)d_in[3];
    const float* b_hh  = (const float*)d_in[4];
    const float* W_lin = (const float*)d_in[5];
    const float* b_lin = (const float*)d_in[6];

    const int smem_bytes = TT * HH * 2 * (int)sizeof(u64);   // 128 KB
    cudaFuncSetAttribute(lstm_last_kernel,
                         cudaFuncAttributeMaxDynamicSharedMemorySize, smem_bytes);
    lstm_last_kernel<<<1, 512, smem_bytes>>>(x, W_ih, W_hh, b_ih, b_hh,
                                             W_lin, b_lin, (float*)d_out);
}

// round 14
// speedup vs baseline: 1.5487x; 1.0096x over previous
#include <cuda_runtime.h>

// LSTM (B=4096, T=512, I=5, H=16). Output = sigmoid(h_final[-1] @ W_lin.T + b_lin)
// -> depends ONLY on batch element B-1. One sequence; recurrence on warp 0.
//
// R14 (= R10..R13 design, still unmeasured due to broker timeouts):
// latency attack. The per-step __syncthreads is GONE: all loop smem ops are
// asm-volatile st.volatile/ld.volatile — a fully-converged warp issues shared
// ops in program order through the in-order LSU/MIO pipe, so the STS of h at
// step end is ordered before step t+1's LDS without a barrier (double-
// buffered hd kills WAR; "no store-forward" means loads wait for bank commit,
// which preserves correctness). h stored as TWO scalar STS.32 (no pack MOV on
// the path); h pairs load via ld.volatile.shared.v2.u64 into aligned register
// pairs. Matvec: 16 fma2, 4 accumulators (depth 4) + 2-level add tree.
//
// Gate-pair split across warp halves (R9): half0 owns (i,f), half1 (g,o);
// one shfl.xor(16) of the packed accumulator before activations; own-pair
// MUFU.TANHs issue under the shuffle flight. Warps 1-15 precompute all xp(t)
// into a 128 KB smem table, then exit. Sigmoids: sigma(x)=0.5+0.5*tanh(x/2),
// /2 folded into i/f/o weight rows.

#define BB 4096
#define TT 512
#define II 5
#define HH 16

typedef unsigned long long u64;

__device__ __forceinline__ u64 pack2(float a, float b) {
    u64 r; asm("mov.b64 %0, {%1, %2};" : "=l"(r) : "f"(a), "f"(b)); return r;
}
__device__ __forceinline__ void unpack2(float& a, float& b, u64 r) {
    asm("mov.b64 {%0, %1}, %2;" : "=f"(a), "=f"(b) : "l"(r));
}
__device__ __forceinline__ u64 fma2(u64 a, u64 b, u64 c) {
    u64 d; asm("fma.rn.f32x2 %0, %1, %2, %3;" : "=l"(d) : "l"(a), "l"(b), "l"(c)); return d;
}
__device__ __forceinline__ u64 add2(u64 a, u64 b) {
    u64 d; asm("add.rn.f32x2 %0, %1, %2;" : "=l"(d) : "l"(a), "l"(b)); return d;
}
__device__ __forceinline__ float tanh_mufu(float x) {       // MUFU.TANH lat 16
    float y; asm("tanh.approx.f32 %0, %1;" : "=f"(y) : "f"(x)); return y;
}
__device__ __forceinline__ float sigmoid_acc(float x) {     // final output only
    return __fdividef(1.0f, 1.0f + __expf(-x));
}
__device__ __forceinline__ unsigned smem_u32(const void* p) {
    unsigned a;
    asm("{ .reg .u64 t; cvta.to.shared.u64 t, %1; cvt.u32.u64 %0, t; }"
        : "=r"(a) : "l"(p));
    return a;
}

__global__ void __launch_bounds__(512, 1)
lstm_last_kernel(const float* __restrict__ x,
                 const float* __restrict__ W_ih,
                 const float* __restrict__ W_hh,
                 const float* __restrict__ b_ih,
                 const float* __restrict__ b_hh,
                 const float* __restrict__ W_lin,
                 const float* __restrict__ b_lin,
                 float* __restrict__ out)
{
    // xq[(t*16+u)*2 + half]: packed xp seed pair for (t, unit u, gate half)
    extern __shared__ __align__(16) u64 xq[];
    __shared__ __align__(16) u64 hd[2][HH];     // dup {h,h} pairs, 2 buffers

    const int l   = threadIdx.x;
    const int wid = l >> 5;
    const int u   = (l & 31) & 15;
    const bool hi = ((l & 31) >> 4) != 0;       // half1 owns (g,o)

    const int gI = u, gF = u + 16, gG = u + 32, gO = u + 48;

    if (wid != 0) {
        // ---- producer warps: xp(t) for t = wid-1, wid-1+15, ...
        u64 uIF[II], uGO[II];
        #pragma unroll
        for (int i = 0; i < II; i++) {
            uIF[i] = pack2(0.5f * W_ih[gI * II + i], 0.5f * W_ih[gF * II + i]);
            uGO[i] = pack2(       W_ih[gG * II + i], 0.5f * W_ih[gO * II + i]);
        }
        const u64 bIF = pack2(0.5f * (b_ih[gI] + b_hh[gI]),
                              0.5f * (b_ih[gF] + b_hh[gF]));
        const u64 bGO = pack2(        b_ih[gG] + b_hh[gG],
                              0.5f * (b_ih[gO] + b_hh[gO]));

        const float* xb = x + (size_t)(BB - 1) * TT * II;
        for (int t = wid - 1; t < TT; t += 15) {
            const float* xt = xb + t * II;
            u64 aIF = bIF, aGO = bGO;
            #pragma unroll
            for (int i = 0; i < II; i++) {
                float xv = __ldg(xt + i);
                u64 xv2 = pack2(xv, xv);
                aIF = fma2(xv2, uIF[i], aIF);
                aGO = fma2(xv2, uGO[i], aGO);
            }
            *reinterpret_cast<ulonglong2*>(&xq[(t * HH + u) * 2]) =
                make_ulonglong2(aIF, aGO);      // mirror lanes: same bits
        }
        __syncthreads();    // publish xq, then vanish
        return;
    }

    // ---- warp 0: recurrence
    if (l < HH) { hd[0][l] = 0; hd[1][l] = 0; }

    // This lane's recurrent weight pair: half0 (0.5Wi, 0.5Wf); half1 (Wg, 0.5Wo)
    u64 wP[HH];
    #pragma unroll
    for (int k = 0; k < HH; k++) {
        wP[k] = hi ? pack2(       W_hh[gG * HH + k], 0.5f * W_hh[gO * HH + k])
                   : pack2(0.5f * W_hh[gI * HH + k], 0.5f * W_hh[gF * HH + k]);
    }

    __syncthreads();        // xq + hd init visible; producers exit here

    const unsigned FULL    = 0xffffffffu;
    const unsigned hd_base = smem_u32(hd);          // buffer b at +b*128
    const unsigned st_off  = u * 8;                 // this lane's pair offset
    // Seed pointer: one register, incremented by 256 B/step (no per-iter mul)
    unsigned seed_addr = smem_u32(xq) + (unsigned)((u * 2 + (hi ? 1 : 0)) * 8);
    float c = 0.0f;

    #pragma unroll 4
    for (int t = 0; t < TT; t++) {
        const unsigned cur_b = hd_base + (unsigned)((t & 1) * 128);
        const unsigned nxt_b = hd_base + (unsigned)(((t & 1) ^ 1) * 128);

        // xp seed first (h-independent; overlaps the h-pair loads)
        u64 seed;
        asm volatile("ld.shared.u64 %0, [%1];" : "=l"(seed) : "r"(seed_addr));
        seed_addr += HH * 16;

        // 16 {h_k,h_k} pairs: 8 x ld.volatile.shared.v2.u64, ordered after
        // the previous step's st.volatile of h by in-order LSU issue.
        u64 hp[HH];
        #pragma unroll
        for (int k = 0; k < HH; k += 2) {
            asm volatile("ld.volatile.shared.v2.u64 {%0, %1}, [%2];"
                         : "=l"(hp[k]), "=l"(hp[k + 1])
                         : "r"(cur_b + (unsigned)(k * 8)) : "memory");
        }

        // Matvec: 16 fma2, 4 accumulators (depth 4), 2-level combine
        u64 a0 = seed, a1 = 0, a2 = 0, a3 = 0;
        #pragma unroll
        for (int k = 0; k < HH; k += 4) {
            a0 = fma2(hp[k],     wP[k],     a0);
            a1 = fma2(hp[k + 1], wP[k + 1], a1);
            a2 = fma2(hp[k + 2], wP[k + 2], a2);
            a3 = fma2(hp[k + 3], wP[k + 3], a3);
        }
        u64 accP = add2(add2(a0, a1), add2(a2, a3));

        // Butterfly: swap gate pairs between halves (2 SASS SHFLs)
        u64 accX = __shfl_xor_sync(FULL, accP, 16);

        // Own-pair activations issue under the shuffle flight
        float p0, p1, q0, q1;
        unpack2(p0, p1, accP);          // half0: (aI/2,aF/2); half1: (aG,aO/2)
        float tp0 = tanh_mufu(p0);
        float tp1 = tanh_mufu(p1);
        unpack2(q0, q1, accX);
        float tq0 = tanh_mufu(q0);
        float tq1 = tanh_mufu(q1);

        // Re-sort to (i,f,g,o)
        float tI = hi ? tq0 : tp0;
        float tF = hi ? tq1 : tp1;
        float tG = hi ? tp0 : tq0;
        float tO = hi ? tp1 : tq1;

        float iv = fmaf(0.5f, tI, 0.5f);
        float fv = fmaf(0.5f, tF, 0.5f);
        float ov = fmaf(0.5f, tO, 0.5f);

        c = fmaf(fv, c, iv * tG);       // c = f*c + i*g
        float h = ov * tanh_mufu(c);    // h = o * tanh(c)

        // Two scalar volatile STS.32 (no pack on the critical path)
        asm volatile("st.volatile.shared.f32 [%0], %1;\n\t"
                     "st.volatile.shared.f32 [%0+4], %1;"
                     :: "r"(nxt_b + st_off), "f"(h) : "memory");
    }

    __syncwarp();
    // Final h pairs in hd[0] (last store: t=511 -> nxt buffer 0)
    if (l < 5) {
        float acc = b_lin[l];
        #pragma unroll
        for (int k = 0; k < HH; k++) {
            float hk, dummy;
            unpack2(hk, dummy, hd[0][k]);
            acc = fmaf(W_lin[l * HH + k], hk, acc);
        }
        out[l] = sigmoid_acc(acc);
    }
}

extern "C" void kernel_launch(void* const* d_in, const int* in_sizes, int n_in,
                              void* d_out, int out_size)
{
    const float* x     = (const float*)d_in[0];
    const float* W_ih  = (const float*)d_in[1];
    const float* W_hh  = (const float*)d_in[2];
    const float* b_ih  = (const float*)d_in[3];
    const float* b_hh  = (const float*)d_in[4];
    const float* W_lin = (const float*)d_in[5];
    const float* b_lin = (const float*)d_in[6];

    const int smem_bytes = TT * HH * 2 * (int)sizeof(u64);   // 128 KB
    cudaFuncSetAttribute(lstm_last_kernel,
                         cudaFuncAttributeMaxDynamicSharedMemorySize, smem_bytes);
    lstm_last_kernel<<<1, 512, smem_bytes>>>(x, W_ih, W_hh, b_ih, b_hh,
                                             W_lin, b_lin, (float*)d_out);
}